// round 12
// baseline (speedup 1.0000x reference)
#include <cuda_runtime.h>
#include <cuda_fp16.h>
#include <cuda_bf16.h>
#include <cstdint>
#include <cstddef>

// Problem constants
#define BSZ   16384
#define DM    1024
#define RR    64
#define EE    4
#define LL    3
#define NPAD  320     // 256 V cols + 4 gate cols, padded to 5*64
#define KW    256     // E*R

// ---------------------------------------------------------------------------
// Static device buffers
// ---------------------------------------------------------------------------
__device__ __align__(256) __half         g_xh[(size_t)BSZ * DM];   // fp16 hi of x_l
__device__ __align__(256) __half         g_xl[(size_t)BSZ * DM];   // fp16 lo of x_l
__device__ __align__(256) float          g_Y[(size_t)BSZ * NPAD];
__device__ __align__(256) __nv_bfloat16  g_wh[(size_t)BSZ * KW];   // bf16 hi of w
__device__ __align__(256) __nv_bfloat16  g_wl[(size_t)BSZ * KW];   // bf16 lo of w
__device__ __align__(256) __half         g_W1h[LL * NPAD * DM];    // fp16 weight hi (GEMM1 B)
__device__ __align__(256) __half         g_W1l[LL * NPAD * DM];    // fp16 weight lo
__device__ __align__(256) __nv_bfloat16  g_Uh[LL * DM * KW];       // bf16 weight hi (GEMM2 B)
__device__ __align__(256) __nv_bfloat16  g_Ul[LL * DM * KW];       // bf16 weight lo

// ---------------------------------------------------------------------------
// PTX helpers (baseline ISA only)
// ---------------------------------------------------------------------------
__device__ __forceinline__ uint32_t s2u(const void* p) {
    uint32_t a;
    asm("{ .reg .u64 t; cvta.to.shared.u64 t, %1; cvt.u32.u64 %0, t; }" : "=r"(a) : "l"(p));
    return a;
}
__device__ __forceinline__ void cpasync16(uint32_t dst, const void* src) {
    asm volatile("cp.async.cg.shared.global [%0], [%1], 16;" :: "r"(dst), "l"(src) : "memory");
}
#define CP_COMMIT() asm volatile("cp.async.commit_group;" ::: "memory")
#define CP_WAIT1()  asm volatile("cp.async.wait_group 1;" ::: "memory")
#define CP_WAIT2()  asm volatile("cp.async.wait_group 2;" ::: "memory")

__device__ __forceinline__ void ldsm4(uint32_t* r, uint32_t addr) {
    asm volatile("ldmatrix.sync.aligned.m8n8.x4.shared.b16 {%0,%1,%2,%3}, [%4];"
                 : "=r"(r[0]), "=r"(r[1]), "=r"(r[2]), "=r"(r[3]) : "r"(addr));
}
__device__ __forceinline__ void mma_f16(float* c, const uint32_t* a, const uint32_t* b) {
    asm volatile(
        "mma.sync.aligned.m16n8k16.row.col.f32.f16.f16.f32 "
        "{%0,%1,%2,%3}, {%4,%5,%6,%7}, {%8,%9}, {%0,%1,%2,%3};"
        : "+f"(c[0]), "+f"(c[1]), "+f"(c[2]), "+f"(c[3])
        : "r"(a[0]), "r"(a[1]), "r"(a[2]), "r"(a[3]), "r"(b[0]), "r"(b[1]));
}
__device__ __forceinline__ void mma_bf16(float* c, const uint32_t* a, const uint32_t* b) {
    asm volatile(
        "mma.sync.aligned.m16n8k16.row.col.f32.bf16.bf16.f32 "
        "{%0,%1,%2,%3}, {%4,%5,%6,%7}, {%8,%9}, {%0,%1,%2,%3};"
        : "+f"(c[0]), "+f"(c[1]), "+f"(c[2]), "+f"(c[3])
        : "r"(a[0]), "r"(a[1]), "r"(a[2]), "r"(a[3]), "r"(b[0]), "r"(b[1]));
}

// FMA-only tanh (no MUFU): tanh(x) = sgn(x)*(1 - 2/(e^{2|x|}+1))
__device__ __forceinline__ float fast_tanh(float x) {
    float ax = fminf(fabsf(x), 9.0f);
    float z = ax * 2.885390082f;                 // 2*log2(e)*|x|
    float k2 = z + 12582912.0f;                  // 1.5*2^23 round trick
    int   ki = __float_as_int(k2) - 0x4B400000;
    float f  = z - (k2 - 12582912.0f);           // frac in [-0.5, 0.5]
    float p = 1.3333558e-3f;
    p = fmaf(p, f, 9.6181291e-3f);
    p = fmaf(p, f, 5.5504109e-2f);
    p = fmaf(p, f, 2.4022651e-1f);
    p = fmaf(p, f, 6.9314718e-1f);
    p = fmaf(p, f, 1.0f);
    float E = p * __int_as_float((ki + 127) << 23);   // e^{2|x|}
    float d = E + 1.0f;
    float r = __int_as_float(0x7EF311C3 - __float_as_int(d));
    r = r * fmaf(-d, r, 2.0f);
    r = r * fmaf(-d, r, 2.0f);
    r = r * fmaf(-d, r, 2.0f);
    float t = fmaf(-2.0f, r, 1.0f);
    return copysignf(t, x);
}

// ---------------------------------------------------------------------------
// GEMM1 (R9/R10-measured 72us): fp16 2-term, D = A @ (Bh+Bl)^T, fp32 accum.
// BM=128, BN=64, WN=32, BK=64 (pitch 144), 3-stage cp.async, 2 CTAs/SM.
// Writes fp32 D to Cout.
// ---------------------------------------------------------------------------
__global__ void __launch_bounds__(256, 2)
gemm1_f16(const __half* __restrict__ Ag,
          const __half* __restrict__ Bgh, const __half* __restrict__ Bgl,
          int bRowOff, float* __restrict__ Cout)
{
    constexpr int BM = 128, BN = 64, WN = 32, BK = 64, KTOT = DM, STAGES = 3;
    constexpr int MF = 2, NF = WN / 8, KS = BK / 16, KCH = KTOT / BK;
    constexpr int PITCH = 2 * BK + 16;
    constexpr int SA = BM * PITCH, SB = BN * PITCH, SST = SA + 2 * SB;

    extern __shared__ __align__(128) char smem[];
    const uint32_t sbase = s2u(smem);

    const int tid = threadIdx.x, lane = tid & 31, wid = tid >> 5;
    const int wm = wid & 3, wn = wid >> 2;
    const int m0 = blockIdx.y * BM;
    const int n0 = bRowOff + blockIdx.x * BN;
    const int c0 = blockIdx.x * BN;
    const int K = KTOT;

    float acc[MF][NF][4];
#pragma unroll
    for (int i = 0; i < MF; ++i)
#pragma unroll
        for (int j = 0; j < NF; ++j)
#pragma unroll
            for (int p = 0; p < 4; ++p) acc[i][j][p] = 0.f;

    auto load_stage = [&](int st, int kt) {
        const uint32_t base = sbase + st * SST;
        const int kk = kt * BK;
        constexpr int CPR = BK / 8;
#pragma unroll
        for (int c = tid; c < BM * CPR; c += 256) {
            const int row = c / CPR, cc = c % CPR;
            cpasync16(base + row * PITCH + cc * 16,
                      Ag + (size_t)(m0 + row) * K + kk + cc * 8);
        }
#pragma unroll
        for (int c = tid; c < BN * CPR; c += 256) {
            const int row = c / CPR, cc = c % CPR;
            const size_t g = (size_t)(n0 + row) * K + kk + cc * 8;
            const uint32_t s = row * PITCH + cc * 16;
            cpasync16(base + SA + s,      Bgh + g);
            cpasync16(base + SA + SB + s, Bgl + g);
        }
    };

#pragma unroll
    for (int s = 0; s < STAGES - 1; ++s) { load_stage(s, s); CP_COMMIT(); }

    const int arow = wm * 32 + (lane & 15);
    const int brow = wn * WN + (lane & 7) + ((lane >> 4) << 3);
    const uint32_t aoff = (uint32_t)arow * PITCH + ((lane >> 4) << 4);
    const uint32_t boff = (uint32_t)brow * PITCH + (((lane >> 3) & 1) << 4);

    for (int kt = 0; kt < KCH; ++kt) {
        if (kt + STAGES - 1 < KCH) load_stage((kt + STAGES - 1) % STAGES, kt + STAGES - 1);
        CP_COMMIT();
        CP_WAIT2();
        __syncthreads();

        const uint32_t sb2 = sbase + (kt % STAGES) * SST;
        const uint32_t ab = sb2 + aoff;
        const uint32_t bbh = sb2 + SA + boff;

#pragma unroll
        for (int ks = 0; ks < KS; ++ks) {
            uint32_t af[MF][4];
#pragma unroll
            for (int mf = 0; mf < MF; ++mf)
                ldsm4(af[mf], ab + mf * 16 * PITCH + ks * 32);
            uint32_t bh[NF][2], bl[NF][2];
#pragma unroll
            for (int nf2 = 0; nf2 < NF / 2; ++nf2) {
                const uint32_t off = bbh + nf2 * 16 * PITCH + ks * 32;
                uint32_t t[4];
                ldsm4(t, off);
                bh[2 * nf2][0] = t[0]; bh[2 * nf2][1] = t[1];
                bh[2 * nf2 + 1][0] = t[2]; bh[2 * nf2 + 1][1] = t[3];
                ldsm4(t, off + SB);
                bl[2 * nf2][0] = t[0]; bl[2 * nf2][1] = t[1];
                bl[2 * nf2 + 1][0] = t[2]; bl[2 * nf2 + 1][1] = t[3];
            }
#pragma unroll
            for (int mf = 0; mf < MF; ++mf)
#pragma unroll
                for (int nf = 0; nf < NF; ++nf)
                    mma_f16(acc[mf][nf], af[mf], bh[nf]);
#pragma unroll
            for (int mf = 0; mf < MF; ++mf)
#pragma unroll
                for (int nf = 0; nf < NF; ++nf)
                    mma_f16(acc[mf][nf], af[mf], bl[nf]);
        }
        __syncthreads();
    }

#pragma unroll
    for (int mf = 0; mf < MF; ++mf)
#pragma unroll
        for (int p = 0; p < 2; ++p) {
            const int m = m0 + wm * 32 + mf * 16 + (lane >> 2) + p * 8;
#pragma unroll
            for (int nf = 0; nf < NF; ++nf) {
                const int col = c0 + wn * WN + nf * 8 + (lane & 3) * 2;
                *reinterpret_cast<float2*>(Cout + (size_t)m * NPAD + col) =
                    make_float2(acc[mf][nf][p * 2], acc[mf][nf][p * 2 + 1]);
            }
        }
}

// ---------------------------------------------------------------------------
// GEMM2 (R8-proven): bf16 3-term, D = (Ah+Al) @ (Bh+Bl)^T (drop Al*Bl).
// BM=128, BN=128, WN=64, BK=32 (pitch 80), 2-stage cp.async, 2 CTAs/SM.
// Epilogue: o = (xh+xl) + x0*(D+bias); MODE 1 writes fp16 xh/xl = split(o),
// MODE 2 writes fp32 o to Cout.  (xh/xl are fp16 — GEMM1's A format.)
// ---------------------------------------------------------------------------
template <int MODE>
__global__ void __launch_bounds__(256, 2)
gemm2_bf16(const __nv_bfloat16* __restrict__ Agh, const __nv_bfloat16* __restrict__ Agl,
           const __nv_bfloat16* __restrict__ Bgh, const __nv_bfloat16* __restrict__ Bgl,
           int bRowOff, float* __restrict__ Cout,
           const float* __restrict__ x0, const float* __restrict__ bias,
           __half* __restrict__ xh, __half* __restrict__ xl)
{
    constexpr int BM = 128, BN = 128, WN = 64, BK = 32, KTOT = KW;
    constexpr int MF = 2, NF = WN / 8, KS = BK / 16, KCH = KTOT / BK;
    constexpr int PITCH = 2 * BK + 16;       // 80
    constexpr int SA = BM * PITCH, SB = BN * PITCH, SST = 2 * SA + 2 * SB;

    extern __shared__ __align__(128) char smem[];
    const uint32_t sbase = s2u(smem);

    const int tid = threadIdx.x, lane = tid & 31, wid = tid >> 5;
    const int wm = wid & 3, wn = wid >> 2;
    const int m0 = blockIdx.y * BM;
    const int n0 = bRowOff + blockIdx.x * BN;
    const int c0 = blockIdx.x * BN;
    const int K = KTOT;

    float acc[MF][NF][4];
#pragma unroll
    for (int i = 0; i < MF; ++i)
#pragma unroll
        for (int j = 0; j < NF; ++j)
#pragma unroll
            for (int p = 0; p < 4; ++p) acc[i][j][p] = 0.f;

    auto load_stage = [&](int st, int kt) {
        const uint32_t base = sbase + st * SST;
        const int kk = kt * BK;
        constexpr int CPR = BK / 8;      // 4
#pragma unroll
        for (int c = tid; c < BM * CPR; c += 256) {
            const int row = c / CPR, cc = c % CPR;
            const size_t g = (size_t)(m0 + row) * K + kk + cc * 8;
            const uint32_t s = row * PITCH + cc * 16;
            cpasync16(base + s,      Agh + g);
            cpasync16(base + SA + s, Agl + g);
        }
#pragma unroll
        for (int c = tid; c < BN * CPR; c += 256) {
            const int row = c / CPR, cc = c % CPR;
            const size_t g = (size_t)(n0 + row) * K + kk + cc * 8;
            const uint32_t s = row * PITCH + cc * 16;
            cpasync16(base + 2 * SA + s,      Bgh + g);
            cpasync16(base + 2 * SA + SB + s, Bgl + g);
        }
    };

    load_stage(0, 0);
    CP_COMMIT();

    const int arow = wm * 32 + (lane & 15);
    const int brow = wn * WN + (lane & 7) + ((lane >> 4) << 3);
    const uint32_t aoff = (uint32_t)arow * PITCH + ((lane >> 4) << 4);
    const uint32_t boff = (uint32_t)brow * PITCH + (((lane >> 3) & 1) << 4);

    for (int kt = 0; kt < KCH; ++kt) {
        if (kt + 1 < KCH) load_stage((kt + 1) & 1, kt + 1);
        CP_COMMIT();
        CP_WAIT1();
        __syncthreads();

        const uint32_t sb2 = sbase + (kt & 1) * SST;
        const uint32_t ab = sb2 + aoff;
        const uint32_t bb = sb2 + 2 * SA + boff;

#pragma unroll
        for (int ks = 0; ks < KS; ++ks) {
            uint32_t ah[MF][4], al[MF][4];
#pragma unroll
            for (int mf = 0; mf < MF; ++mf) {
                const uint32_t off = ab + mf * 16 * PITCH + ks * 32;
                ldsm4(ah[mf], off);
                ldsm4(al[mf], off + SA);
            }
            uint32_t bh[NF][2], bl[NF][2];
#pragma unroll
            for (int nf2 = 0; nf2 < NF / 2; ++nf2) {
                const uint32_t off = bb + nf2 * 16 * PITCH + ks * 32;
                uint32_t t[4];
                ldsm4(t, off);
                bh[2 * nf2][0] = t[0]; bh[2 * nf2][1] = t[1];
                bh[2 * nf2 + 1][0] = t[2]; bh[2 * nf2 + 1][1] = t[3];
                ldsm4(t, off + SB);
                bl[2 * nf2][0] = t[0]; bl[2 * nf2][1] = t[1];
                bl[2 * nf2 + 1][0] = t[2]; bl[2 * nf2 + 1][1] = t[3];
            }
#pragma unroll
            for (int mf = 0; mf < MF; ++mf)
#pragma unroll
                for (int nf = 0; nf < NF; ++nf) {
                    mma_bf16(acc[mf][nf], ah[mf], bh[nf]);
                    mma_bf16(acc[mf][nf], ah[mf], bl[nf]);
                    mma_bf16(acc[mf][nf], al[mf], bh[nf]);
                }
        }
        __syncthreads();
    }

    // Epilogue: o = (xh+xl) + x0*(D+bias)
#pragma unroll
    for (int mf = 0; mf < MF; ++mf)
#pragma unroll
        for (int p = 0; p < 2; ++p) {
            const int m = m0 + wm * 32 + mf * 16 + (lane >> 2) + p * 8;
#pragma unroll
            for (int nf = 0; nf < NF; ++nf) {
                const int col = c0 + wn * WN + nf * 8 + (lane & 3) * 2;
                const size_t off = (size_t)m * DM + col;
                const float v0 = acc[mf][nf][p * 2];
                const float v1 = acc[mf][nf][p * 2 + 1];
                const float2 xz = *reinterpret_cast<const float2*>(x0 + off);
                const float2 bb2 = *reinterpret_cast<const float2*>(bias + col);
                const __half2 hv = *reinterpret_cast<const __half2*>(xh + off);
                const __half2 lv = *reinterpret_cast<const __half2*>(xl + off);
                const float xp0 = __half2float(hv.x) + __half2float(lv.x);
                const float xp1 = __half2float(hv.y) + __half2float(lv.y);
                const float o0 = fmaf(xz.x, v0 + bb2.x, xp0);
                const float o1 = fmaf(xz.y, v1 + bb2.y, xp1);
                if constexpr (MODE == 1) {
                    const __half h0 = __float2half(o0);
                    const __half h1 = __float2half(o1);
                    __half2 hp; hp.x = h0; hp.y = h1;
                    *reinterpret_cast<__half2*>(xh + off) = hp;
                    __half2 lp;
                    lp.x = __float2half(o0 - __half2float(h0));
                    lp.y = __float2half(o1 - __half2float(h1));
                    *reinterpret_cast<__half2*>(xl + off) = lp;
                } else {
                    *reinterpret_cast<float2*>(Cout + off) = make_float2(o0, o1);
                }
            }
        }
}

// ---------------------------------------------------------------------------
// Mix kernel (R8-proven): tanh -> C -> tanh -> softmax gates -> bf16 wh/wl
// ---------------------------------------------------------------------------
__global__ void __launch_bounds__(256) mix_kernel(const float* __restrict__ Y,
                                                  const float* __restrict__ Cl,
                                                  __nv_bfloat16* __restrict__ Wh,
                                                  __nv_bfloat16* __restrict__ Wl)
{
    extern __shared__ float Cs[];          // 64 KB: Cs[(e*64+s)*64 + r] = C[e,r,s]
    __shared__ float vt[8][EE * RR];
    __shared__ float gs[8][EE];

    const int tid = threadIdx.x;
    for (int idx = tid; idx < EE * RR * RR; idx += 256) {
        int e = idx >> 12, rem = idx & 4095, s = rem >> 6, r = rem & 63;
        Cs[idx] = Cl[((size_t)e * RR + r) * RR + s];
    }
    __syncthreads();

    const int e = tid >> 6;
    const float* cp = Cs + e * (RR * RR) + (tid & 63);
    const int row0 = blockIdx.x * 64;

    for (int it = 0; it < 8; ++it) {
        const int row = row0 + it * 8;
#pragma unroll
        for (int q = 0; q < 8; ++q)
            vt[q][tid] = fast_tanh(Y[(size_t)(row + q) * NPAD + tid]);
        if (tid < 8) {
            const float* yr = Y + (size_t)(row + tid) * NPAD + EE * RR;
            const float l0 = yr[0], l1 = yr[1], l2 = yr[2], l3 = yr[3];
            const float mx = fmaxf(fmaxf(l0, l1), fmaxf(l2, l3));
            const float e0 = __expf(l0 - mx), e1 = __expf(l1 - mx);
            const float e2 = __expf(l2 - mx), e3 = __expf(l3 - mx);
            const float inv = __frcp_rn(e0 + e1 + e2 + e3);
            gs[tid][0] = e0 * inv; gs[tid][1] = e1 * inv;
            gs[tid][2] = e2 * inv; gs[tid][3] = e3 * inv;
        }
        __syncthreads();

        float a[8];
#pragma unroll
        for (int q = 0; q < 8; ++q) a[q] = 0.f;
#pragma unroll
        for (int s = 0; s < RR; ++s) {
            const float c = cp[s * RR];
#pragma unroll
            for (int q = 0; q < 8; ++q)
                a[q] = fmaf(c, vt[q][e * RR + s], a[q]);
        }
#pragma unroll
        for (int q = 0; q < 8; ++q) {
            const float w = gs[q][e] * fast_tanh(a[q]);
            const __nv_bfloat16 h = __float2bfloat16(w);
            Wh[(size_t)(row + q) * KW + tid] = h;
            Wl[(size_t)(row + q) * KW + tid] = __float2bfloat16(w - __bfloat162float(h));
        }
        __syncthreads();
    }
}

// ---------------------------------------------------------------------------
// Conversion + weight packing
// ---------------------------------------------------------------------------
__global__ void conv_kernel(const float* __restrict__ x,
                            __half* __restrict__ xh, __half* __restrict__ xl) {
    const size_t i = ((size_t)blockIdx.x * blockDim.x + threadIdx.x) * 4;
    const float4 v = *reinterpret_cast<const float4*>(x + i);
    __half h0 = __float2half(v.x), h1 = __float2half(v.y);
    __half h2 = __float2half(v.z), h3 = __float2half(v.w);
    __half2 hp0; hp0.x = h0; hp0.y = h1;
    __half2 hp1; hp1.x = h2; hp1.y = h3;
    *reinterpret_cast<__half2*>(xh + i)     = hp0;
    *reinterpret_cast<__half2*>(xh + i + 2) = hp1;
    __half2 lp0, lp1;
    lp0.x = __float2half(v.x - __half2float(h0));
    lp0.y = __float2half(v.y - __half2float(h1));
    lp1.x = __float2half(v.z - __half2float(h2));
    lp1.y = __float2half(v.w - __half2float(h3));
    *reinterpret_cast<__half2*>(xl + i)     = lp0;
    *reinterpret_cast<__half2*>(xl + i + 2) = lp1;
}

__global__ void pack_w1_kernel(const float* __restrict__ V, const float* __restrict__ gw,
                               __half* __restrict__ Wh, __half* __restrict__ Wl) {
    const int idx = blockIdx.x * blockDim.x + threadIdx.x;
    if (idx >= LL * NPAD * DM) return;
    const int i = idx / (NPAD * DM);
    const int rem = idx % (NPAD * DM);
    const int n = rem / DM, d = rem % DM;
    float v = 0.f;
    if (n < EE * RR)
        v = V[(((size_t)i * EE + (n >> 6)) * DM + d) * RR + (n & 63)];
    else if (n < EE * RR + EE)
        v = gw[(size_t)(n - EE * RR) * DM + d];
    const __half h = __float2half(v);
    Wh[idx] = h;
    Wl[idx] = __float2half(v - __half2float(h));
}

__global__ void pack_u_kernel(const float* __restrict__ U,
                              __nv_bfloat16* __restrict__ Uh, __nv_bfloat16* __restrict__ Ul) {
    const int idx = blockIdx.x * blockDim.x + threadIdx.x;
    if (idx >= LL * DM * KW) return;
    const int i = idx / (DM * KW);
    const int rem = idx % (DM * KW);
    const int d = rem / KW, k = rem % KW;
    const float v = U[(((size_t)i * EE + (k >> 6)) * DM + d) * RR + (k & 63)];
    const __nv_bfloat16 h = __float2bfloat16(v);
    Uh[idx] = h;
    Ul[idx] = __float2bfloat16(v - __bfloat162float(h));
}

// ---------------------------------------------------------------------------
// Launch
// ---------------------------------------------------------------------------
extern "C" void kernel_launch(void* const* d_in, const int* in_sizes, int n_in,
                              void* d_out, int out_size) {
    const float* x0   = (const float*)d_in[0];
    const float* U    = (const float*)d_in[1];
    const float* V    = (const float*)d_in[2];
    const float* C    = (const float*)d_in[3];
    const float* gw   = (const float*)d_in[4];
    const float* bias = (const float*)d_in[5];
    float* out = (float*)d_out;

    float* Y = nullptr;
    __half *xh, *xl, *w1h, *w1l;
    __nv_bfloat16 *wh, *wl, *uh, *ul;
    cudaGetSymbolAddress((void**)&Y,   g_Y);
    cudaGetSymbolAddress((void**)&xh,  g_xh);
    cudaGetSymbolAddress((void**)&xl,  g_xl);
    cudaGetSymbolAddress((void**)&wh,  g_wh);
    cudaGetSymbolAddress((void**)&wl,  g_wl);
    cudaGetSymbolAddress((void**)&w1h, g_W1h);
    cudaGetSymbolAddress((void**)&w1l, g_W1l);
    cudaGetSymbolAddress((void**)&uh,  g_Uh);
    cudaGetSymbolAddress((void**)&ul,  g_Ul);

    // GEMM1: 3 stages * (128*144 + 2*64*144) = 110592 B -> 2 CTAs/SM
    // GEMM2: 2 stages * (2*128*80 + 2*128*80) = 81920 B -> 2 CTAs/SM
    constexpr int SMEM1 = 3 * (128 * 144 + 2 * 64 * 144);
    constexpr int SMEM2 = 2 * (2 * 128 * 80 + 2 * 128 * 80);
    cudaFuncSetAttribute((const void*)gemm1_f16,
                         cudaFuncAttributeMaxDynamicSharedMemorySize, SMEM1);
    cudaFuncSetAttribute((const void*)gemm2_bf16<1>,
                         cudaFuncAttributeMaxDynamicSharedMemorySize, SMEM2);
    cudaFuncSetAttribute((const void*)gemm2_bf16<2>,
                         cudaFuncAttributeMaxDynamicSharedMemorySize, SMEM2);
    cudaFuncSetAttribute((const void*)mix_kernel,
                         cudaFuncAttributeMaxDynamicSharedMemorySize, EE * RR * RR * 4);

    // Pack weights + initial x conversion
    pack_w1_kernel<<<(LL * NPAD * DM + 255) / 256, 256>>>(V, gw, w1h, w1l);
    pack_u_kernel<<<(LL * DM * KW + 255) / 256, 256>>>(U, uh, ul);
    conv_kernel<<<(BSZ * DM / 4) / 256, 256>>>(x0, xh, xl);

    for (int i = 0; i < LL; ++i) {
        // GEMM1: Y[B,320] = xh @ [V|gate]^T   (fp16 2-term, measured 72us)
        gemm1_f16<<<dim3(NPAD / 64, BSZ / 128), 256, SMEM1>>>(
            xh, w1h, w1l, i * NPAD, Y);

        // Mix: tanh -> C -> tanh -> softmax gates -> bf16 wh/wl
        mix_kernel<<<BSZ / 64, 256, EE * RR * RR * 4>>>(
            Y, C + (size_t)i * EE * RR * RR, wh, wl);

        // GEMM2 + fused epilogue (bf16x3, R8-proven): x_{l+1} = (xh+xl) + x0*(w@U^T + bias)
        if (i < LL - 1) {
            gemm2_bf16<1><<<dim3(DM / 128, BSZ / 128), 256, SMEM2>>>(
                wh, wl, uh, ul, i * DM,
                nullptr, x0, bias + (size_t)i * DM, xh, xl);
        } else {
            gemm2_bf16<2><<<dim3(DM / 128, BSZ / 128), 256, SMEM2>>>(
                wh, wl, uh, ul, i * DM,
                out, x0, bias + (size_t)i * DM, xh, xl);
        }
    }
}

// round 13
// speedup vs baseline: 1.1952x; 1.1952x over previous
#include <cuda_runtime.h>
#include <cuda_fp16.h>
#include <cuda_bf16.h>
#include <cstdint>
#include <cstddef>

// Problem constants
#define BSZ   16384
#define DM    1024
#define RR    64
#define EE    4
#define LL    3
#define NPAD  320     // 256 V cols + 4 gate cols, padded to 5*64
#define KW    256     // E*R

// ---------------------------------------------------------------------------
// Static device buffers
// ---------------------------------------------------------------------------
__device__ __align__(256) __half         g_xh[(size_t)BSZ * DM];   // fp16 hi of x_l
__device__ __align__(256) __half         g_xl[(size_t)BSZ * DM];   // fp16 lo of x_l
__device__ __align__(256) float          g_Y[(size_t)BSZ * NPAD];
__device__ __align__(256) __nv_bfloat16  g_wh[(size_t)BSZ * KW];   // bf16 hi of w
__device__ __align__(256) __nv_bfloat16  g_wl[(size_t)BSZ * KW];   // bf16 lo of w
__device__ __align__(256) __half         g_W1h[LL * NPAD * DM];    // fp16 weight hi (GEMM1 B)
__device__ __align__(256) __half         g_W1l[LL * NPAD * DM];    // fp16 weight lo
__device__ __align__(256) __nv_bfloat16  g_Uh[LL * DM * KW];       // bf16 weight hi (GEMM2 B)
__device__ __align__(256) __nv_bfloat16  g_Ul[LL * DM * KW];       // bf16 weight lo

// ---------------------------------------------------------------------------
// PTX helpers (baseline ISA only)
// ---------------------------------------------------------------------------
__device__ __forceinline__ uint32_t s2u(const void* p) {
    uint32_t a;
    asm("{ .reg .u64 t; cvta.to.shared.u64 t, %1; cvt.u32.u64 %0, t; }" : "=r"(a) : "l"(p));
    return a;
}
__device__ __forceinline__ void cpasync16(uint32_t dst, const void* src) {
    asm volatile("cp.async.cg.shared.global [%0], [%1], 16;" :: "r"(dst), "l"(src) : "memory");
}
#define CP_COMMIT() asm volatile("cp.async.commit_group;" ::: "memory")
#define CP_WAIT1()  asm volatile("cp.async.wait_group 1;" ::: "memory")
#define CP_WAIT2()  asm volatile("cp.async.wait_group 2;" ::: "memory")

__device__ __forceinline__ void ldsm4(uint32_t* r, uint32_t addr) {
    asm volatile("ldmatrix.sync.aligned.m8n8.x4.shared.b16 {%0,%1,%2,%3}, [%4];"
                 : "=r"(r[0]), "=r"(r[1]), "=r"(r[2]), "=r"(r[3]) : "r"(addr));
}
__device__ __forceinline__ void mma_f16(float* c, const uint32_t* a, const uint32_t* b) {
    asm volatile(
        "mma.sync.aligned.m16n8k16.row.col.f32.f16.f16.f32 "
        "{%0,%1,%2,%3}, {%4,%5,%6,%7}, {%8,%9}, {%0,%1,%2,%3};"
        : "+f"(c[0]), "+f"(c[1]), "+f"(c[2]), "+f"(c[3])
        : "r"(a[0]), "r"(a[1]), "r"(a[2]), "r"(a[3]), "r"(b[0]), "r"(b[1]));
}
__device__ __forceinline__ void mma_bf16(float* c, const uint32_t* a, const uint32_t* b) {
    asm volatile(
        "mma.sync.aligned.m16n8k16.row.col.f32.bf16.bf16.f32 "
        "{%0,%1,%2,%3}, {%4,%5,%6,%7}, {%8,%9}, {%0,%1,%2,%3};"
        : "+f"(c[0]), "+f"(c[1]), "+f"(c[2]), "+f"(c[3])
        : "r"(a[0]), "r"(a[1]), "r"(a[2]), "r"(a[3]), "r"(b[0]), "r"(b[1]));
}

// FMA-only tanh (no MUFU): tanh(x) = sgn(x)*(1 - 2/(e^{2|x|}+1))
__device__ __forceinline__ float fast_tanh(float x) {
    float ax = fminf(fabsf(x), 9.0f);
    float z = ax * 2.885390082f;                 // 2*log2(e)*|x|
    float k2 = z + 12582912.0f;                  // 1.5*2^23 round trick
    int   ki = __float_as_int(k2) - 0x4B400000;
    float f  = z - (k2 - 12582912.0f);           // frac in [-0.5, 0.5]
    float p = 1.3333558e-3f;
    p = fmaf(p, f, 9.6181291e-3f);
    p = fmaf(p, f, 5.5504109e-2f);
    p = fmaf(p, f, 2.4022651e-1f);
    p = fmaf(p, f, 6.9314718e-1f);
    p = fmaf(p, f, 1.0f);
    float E = p * __int_as_float((ki + 127) << 23);   // e^{2|x|}
    float d = E + 1.0f;
    float r = __int_as_float(0x7EF311C3 - __float_as_int(d));
    r = r * fmaf(-d, r, 2.0f);
    r = r * fmaf(-d, r, 2.0f);
    r = r * fmaf(-d, r, 2.0f);
    float t = fmaf(-2.0f, r, 1.0f);
    return copysignf(t, x);
}

// ---------------------------------------------------------------------------
// GEMM1 (R9/R10-measured 72us): fp16 2-term, D = A @ (Bh+Bl)^T, fp32 accum.
// BM=128, BN=64, WN=32, BK=64 (pitch 144), 3-stage cp.async, 2 CTAs/SM.
// Writes fp32 D to Cout.
// ---------------------------------------------------------------------------
__global__ void __launch_bounds__(256, 2)
gemm1_f16(const __half* __restrict__ Ag,
          const __half* __restrict__ Bgh, const __half* __restrict__ Bgl,
          int bRowOff, float* __restrict__ Cout)
{
    constexpr int BM = 128, BN = 64, WN = 32, BK = 64, KTOT = DM, STAGES = 3;
    constexpr int MF = 2, NF = WN / 8, KS = BK / 16, KCH = KTOT / BK;
    constexpr int PITCH = 2 * BK + 16;
    constexpr int SA = BM * PITCH, SB = BN * PITCH, SST = SA + 2 * SB;

    extern __shared__ __align__(128) char smem[];
    const uint32_t sbase = s2u(smem);

    const int tid = threadIdx.x, lane = tid & 31, wid = tid >> 5;
    const int wm = wid & 3, wn = wid >> 2;
    const int m0 = blockIdx.y * BM;
    const int n0 = bRowOff + blockIdx.x * BN;
    const int c0 = blockIdx.x * BN;
    const int K = KTOT;

    float acc[MF][NF][4];
#pragma unroll
    for (int i = 0; i < MF; ++i)
#pragma unroll
        for (int j = 0; j < NF; ++j)
#pragma unroll
            for (int p = 0; p < 4; ++p) acc[i][j][p] = 0.f;

    auto load_stage = [&](int st, int kt) {
        const uint32_t base = sbase + st * SST;
        const int kk = kt * BK;
        constexpr int CPR = BK / 8;
#pragma unroll
        for (int c = tid; c < BM * CPR; c += 256) {
            const int row = c / CPR, cc = c % CPR;
            cpasync16(base + row * PITCH + cc * 16,
                      Ag + (size_t)(m0 + row) * K + kk + cc * 8);
        }
#pragma unroll
        for (int c = tid; c < BN * CPR; c += 256) {
            const int row = c / CPR, cc = c % CPR;
            const size_t g = (size_t)(n0 + row) * K + kk + cc * 8;
            const uint32_t s = row * PITCH + cc * 16;
            cpasync16(base + SA + s,      Bgh + g);
            cpasync16(base + SA + SB + s, Bgl + g);
        }
    };

#pragma unroll
    for (int s = 0; s < STAGES - 1; ++s) { load_stage(s, s); CP_COMMIT(); }

    const int arow = wm * 32 + (lane & 15);
    const int brow = wn * WN + (lane & 7) + ((lane >> 4) << 3);
    const uint32_t aoff = (uint32_t)arow * PITCH + ((lane >> 4) << 4);
    const uint32_t boff = (uint32_t)brow * PITCH + (((lane >> 3) & 1) << 4);

    for (int kt = 0; kt < KCH; ++kt) {
        if (kt + STAGES - 1 < KCH) load_stage((kt + STAGES - 1) % STAGES, kt + STAGES - 1);
        CP_COMMIT();
        CP_WAIT2();
        __syncthreads();

        const uint32_t sb2 = sbase + (kt % STAGES) * SST;
        const uint32_t ab = sb2 + aoff;
        const uint32_t bbh = sb2 + SA + boff;

#pragma unroll
        for (int ks = 0; ks < KS; ++ks) {
            uint32_t af[MF][4];
#pragma unroll
            for (int mf = 0; mf < MF; ++mf)
                ldsm4(af[mf], ab + mf * 16 * PITCH + ks * 32);
            uint32_t bh[NF][2], bl[NF][2];
#pragma unroll
            for (int nf2 = 0; nf2 < NF / 2; ++nf2) {
                const uint32_t off = bbh + nf2 * 16 * PITCH + ks * 32;
                uint32_t t[4];
                ldsm4(t, off);
                bh[2 * nf2][0] = t[0]; bh[2 * nf2][1] = t[1];
                bh[2 * nf2 + 1][0] = t[2]; bh[2 * nf2 + 1][1] = t[3];
                ldsm4(t, off + SB);
                bl[2 * nf2][0] = t[0]; bl[2 * nf2][1] = t[1];
                bl[2 * nf2 + 1][0] = t[2]; bl[2 * nf2 + 1][1] = t[3];
            }
#pragma unroll
            for (int mf = 0; mf < MF; ++mf)
#pragma unroll
                for (int nf = 0; nf < NF; ++nf)
                    mma_f16(acc[mf][nf], af[mf], bh[nf]);
#pragma unroll
            for (int mf = 0; mf < MF; ++mf)
#pragma unroll
                for (int nf = 0; nf < NF; ++nf)
                    mma_f16(acc[mf][nf], af[mf], bl[nf]);
        }
        __syncthreads();
    }

#pragma unroll
    for (int mf = 0; mf < MF; ++mf)
#pragma unroll
        for (int p = 0; p < 2; ++p) {
            const int m = m0 + wm * 32 + mf * 16 + (lane >> 2) + p * 8;
#pragma unroll
            for (int nf = 0; nf < NF; ++nf) {
                const int col = c0 + wn * WN + nf * 8 + (lane & 3) * 2;
                *reinterpret_cast<float2*>(Cout + (size_t)m * NPAD + col) =
                    make_float2(acc[mf][nf][p * 2], acc[mf][nf][p * 2 + 1]);
            }
        }
}

// ---------------------------------------------------------------------------
// GEMM2 (R8-proven): bf16 3-term, D = (Ah+Al) @ (Bh+Bl)^T (drop Al*Bl).
// BM=128, BN=128, WN=64, BK=32 (pitch 80), 2-stage cp.async, 2 CTAs/SM.
// Epilogue: o = (xh+xl) + x0*(D+bias); MODE 1 writes fp16 xh/xl = split(o),
// MODE 2 writes fp32 o to Cout.  (xh/xl are fp16 — GEMM1's A format.)
// ---------------------------------------------------------------------------
template <int MODE>
__global__ void __launch_bounds__(256, 2)
gemm2_bf16(const __nv_bfloat16* __restrict__ Agh, const __nv_bfloat16* __restrict__ Agl,
           const __nv_bfloat16* __restrict__ Bgh, const __nv_bfloat16* __restrict__ Bgl,
           int bRowOff, float* __restrict__ Cout,
           const float* __restrict__ x0, const float* __restrict__ bias,
           __half* __restrict__ xh, __half* __restrict__ xl)
{
    constexpr int BM = 128, BN = 128, WN = 64, BK = 32, KTOT = KW;
    constexpr int MF = 2, NF = WN / 8, KS = BK / 16, KCH = KTOT / BK;
    constexpr int PITCH = 2 * BK + 16;       // 80
    constexpr int SA = BM * PITCH, SB = BN * PITCH, SST = 2 * SA + 2 * SB;

    extern __shared__ __align__(128) char smem[];
    const uint32_t sbase = s2u(smem);

    const int tid = threadIdx.x, lane = tid & 31, wid = tid >> 5;
    const int wm = wid & 3, wn = wid >> 2;
    const int m0 = blockIdx.y * BM;
    const int n0 = bRowOff + blockIdx.x * BN;
    const int c0 = blockIdx.x * BN;
    const int K = KTOT;

    float acc[MF][NF][4];
#pragma unroll
    for (int i = 0; i < MF; ++i)
#pragma unroll
        for (int j = 0; j < NF; ++j)
#pragma unroll
            for (int p = 0; p < 4; ++p) acc[i][j][p] = 0.f;

    auto load_stage = [&](int st, int kt) {
        const uint32_t base = sbase + st * SST;
        const int kk = kt * BK;
        constexpr int CPR = BK / 8;      // 4
#pragma unroll
        for (int c = tid; c < BM * CPR; c += 256) {
            const int row = c / CPR, cc = c % CPR;
            const size_t g = (size_t)(m0 + row) * K + kk + cc * 8;
            const uint32_t s = row * PITCH + cc * 16;
            cpasync16(base + s,      Agh + g);
            cpasync16(base + SA + s, Agl + g);
        }
#pragma unroll
        for (int c = tid; c < BN * CPR; c += 256) {
            const int row = c / CPR, cc = c % CPR;
            const size_t g = (size_t)(n0 + row) * K + kk + cc * 8;
            const uint32_t s = row * PITCH + cc * 16;
            cpasync16(base + 2 * SA + s,      Bgh + g);
            cpasync16(base + 2 * SA + SB + s, Bgl + g);
        }
    };

    load_stage(0, 0);
    CP_COMMIT();

    const int arow = wm * 32 + (lane & 15);
    const int brow = wn * WN + (lane & 7) + ((lane >> 4) << 3);
    const uint32_t aoff = (uint32_t)arow * PITCH + ((lane >> 4) << 4);
    const uint32_t boff = (uint32_t)brow * PITCH + (((lane >> 3) & 1) << 4);

    for (int kt = 0; kt < KCH; ++kt) {
        if (kt + 1 < KCH) load_stage((kt + 1) & 1, kt + 1);
        CP_COMMIT();
        CP_WAIT1();
        __syncthreads();

        const uint32_t sb2 = sbase + (kt & 1) * SST;
        const uint32_t ab = sb2 + aoff;
        const uint32_t bb = sb2 + 2 * SA + boff;

#pragma unroll
        for (int ks = 0; ks < KS; ++ks) {
            uint32_t ah[MF][4], al[MF][4];
#pragma unroll
            for (int mf = 0; mf < MF; ++mf) {
                const uint32_t off = ab + mf * 16 * PITCH + ks * 32;
                ldsm4(ah[mf], off);
                ldsm4(al[mf], off + SA);
            }
            uint32_t bh[NF][2], bl[NF][2];
#pragma unroll
            for (int nf2 = 0; nf2 < NF / 2; ++nf2) {
                const uint32_t off = bb + nf2 * 16 * PITCH + ks * 32;
                uint32_t t[4];
                ldsm4(t, off);
                bh[2 * nf2][0] = t[0]; bh[2 * nf2][1] = t[1];
                bh[2 * nf2 + 1][0] = t[2]; bh[2 * nf2 + 1][1] = t[3];
                ldsm4(t, off + SB);
                bl[2 * nf2][0] = t[0]; bl[2 * nf2][1] = t[1];
                bl[2 * nf2 + 1][0] = t[2]; bl[2 * nf2 + 1][1] = t[3];
            }
#pragma unroll
            for (int mf = 0; mf < MF; ++mf)
#pragma unroll
                for (int nf = 0; nf < NF; ++nf) {
                    mma_bf16(acc[mf][nf], ah[mf], bh[nf]);
                    mma_bf16(acc[mf][nf], ah[mf], bl[nf]);
                    mma_bf16(acc[mf][nf], al[mf], bh[nf]);
                }
        }
        __syncthreads();
    }

    // Epilogue: o = (xh+xl) + x0*(D+bias)
#pragma unroll
    for (int mf = 0; mf < MF; ++mf)
#pragma unroll
        for (int p = 0; p < 2; ++p) {
            const int m = m0 + wm * 32 + mf * 16 + (lane >> 2) + p * 8;
#pragma unroll
            for (int nf = 0; nf < NF; ++nf) {
                const int col = c0 + wn * WN + nf * 8 + (lane & 3) * 2;
                const size_t off = (size_t)m * DM + col;
                const float v0 = acc[mf][nf][p * 2];
                const float v1 = acc[mf][nf][p * 2 + 1];
                const float2 xz = *reinterpret_cast<const float2*>(x0 + off);
                const float2 bb2 = *reinterpret_cast<const float2*>(bias + col);
                const __half2 hv = *reinterpret_cast<const __half2*>(xh + off);
                const __half2 lv = *reinterpret_cast<const __half2*>(xl + off);
                const float xp0 = __half2float(hv.x) + __half2float(lv.x);
                const float xp1 = __half2float(hv.y) + __half2float(lv.y);
                const float o0 = fmaf(xz.x, v0 + bb2.x, xp0);
                const float o1 = fmaf(xz.y, v1 + bb2.y, xp1);
                if constexpr (MODE == 1) {
                    const __half h0 = __float2half(o0);
                    const __half h1 = __float2half(o1);
                    __half2 hp; hp.x = h0; hp.y = h1;
                    *reinterpret_cast<__half2*>(xh + off) = hp;
                    __half2 lp;
                    lp.x = __float2half(o0 - __half2float(h0));
                    lp.y = __float2half(o1 - __half2float(h1));
                    *reinterpret_cast<__half2*>(xl + off) = lp;
                } else {
                    *reinterpret_cast<float2*>(Cout + off) = make_float2(o0, o1);
                }
            }
        }
}

// ---------------------------------------------------------------------------
// Mix kernel (R8-proven): tanh -> C -> tanh -> softmax gates -> bf16 wh/wl
// ---------------------------------------------------------------------------
__global__ void __launch_bounds__(256) mix_kernel(const float* __restrict__ Y,
                                                  const float* __restrict__ Cl,
                                                  __nv_bfloat16* __restrict__ Wh,
                                                  __nv_bfloat16* __restrict__ Wl)
{
    extern __shared__ float Cs[];          // 64 KB: Cs[(e*64+s)*64 + r] = C[e,r,s]
    __shared__ float vt[8][EE * RR];
    __shared__ float gs[8][EE];

    const int tid = threadIdx.x;
    for (int idx = tid; idx < EE * RR * RR; idx += 256) {
        int e = idx >> 12, rem = idx & 4095, s = rem >> 6, r = rem & 63;
        Cs[idx] = Cl[((size_t)e * RR + r) * RR + s];
    }
    __syncthreads();

    const int e = tid >> 6;
    const float* cp = Cs + e * (RR * RR) + (tid & 63);
    const int row0 = blockIdx.x * 64;

    for (int it = 0; it < 8; ++it) {
        const int row = row0 + it * 8;
#pragma unroll
        for (int q = 0; q < 8; ++q)
            vt[q][tid] = fast_tanh(Y[(size_t)(row + q) * NPAD + tid]);
        if (tid < 8) {
            const float* yr = Y + (size_t)(row + tid) * NPAD + EE * RR;
            const float l0 = yr[0], l1 = yr[1], l2 = yr[2], l3 = yr[3];
            const float mx = fmaxf(fmaxf(l0, l1), fmaxf(l2, l3));
            const float e0 = __expf(l0 - mx), e1 = __expf(l1 - mx);
            const float e2 = __expf(l2 - mx), e3 = __expf(l3 - mx);
            const float inv = __frcp_rn(e0 + e1 + e2 + e3);
            gs[tid][0] = e0 * inv; gs[tid][1] = e1 * inv;
            gs[tid][2] = e2 * inv; gs[tid][3] = e3 * inv;
        }
        __syncthreads();

        float a[8];
#pragma unroll
        for (int q = 0; q < 8; ++q) a[q] = 0.f;
#pragma unroll
        for (int s = 0; s < RR; ++s) {
            const float c = cp[s * RR];
#pragma unroll
            for (int q = 0; q < 8; ++q)
                a[q] = fmaf(c, vt[q][e * RR + s], a[q]);
        }
#pragma unroll
        for (int q = 0; q < 8; ++q) {
            const float w = gs[q][e] * fast_tanh(a[q]);
            const __nv_bfloat16 h = __float2bfloat16(w);
            Wh[(size_t)(row + q) * KW + tid] = h;
            Wl[(size_t)(row + q) * KW + tid] = __float2bfloat16(w - __bfloat162float(h));
        }
        __syncthreads();
    }
}

// ---------------------------------------------------------------------------
// Conversion + weight packing
// ---------------------------------------------------------------------------
__global__ void conv_kernel(const float* __restrict__ x,
                            __half* __restrict__ xh, __half* __restrict__ xl) {
    const size_t i = ((size_t)blockIdx.x * blockDim.x + threadIdx.x) * 4;
    const float4 v = *reinterpret_cast<const float4*>(x + i);
    __half h0 = __float2half(v.x), h1 = __float2half(v.y);
    __half h2 = __float2half(v.z), h3 = __float2half(v.w);
    __half2 hp0; hp0.x = h0; hp0.y = h1;
    __half2 hp1; hp1.x = h2; hp1.y = h3;
    *reinterpret_cast<__half2*>(xh + i)     = hp0;
    *reinterpret_cast<__half2*>(xh + i + 2) = hp1;
    __half2 lp0, lp1;
    lp0.x = __float2half(v.x - __half2float(h0));
    lp0.y = __float2half(v.y - __half2float(h1));
    lp1.x = __float2half(v.z - __half2float(h2));
    lp1.y = __float2half(v.w - __half2float(h3));
    *reinterpret_cast<__half2*>(xl + i)     = lp0;
    *reinterpret_cast<__half2*>(xl + i + 2) = lp1;
}

__global__ void pack_w1_kernel(const float* __restrict__ V, const float* __restrict__ gw,
                               __half* __restrict__ Wh, __half* __restrict__ Wl) {
    const int idx = blockIdx.x * blockDim.x + threadIdx.x;
    if (idx >= LL * NPAD * DM) return;
    const int i = idx / (NPAD * DM);
    const int rem = idx % (NPAD * DM);
    const int n = rem / DM, d = rem % DM;
    float v = 0.f;
    if (n < EE * RR)
        v = V[(((size_t)i * EE + (n >> 6)) * DM + d) * RR + (n & 63)];
    else if (n < EE * RR + EE)
        v = gw[(size_t)(n - EE * RR) * DM + d];
    const __half h = __float2half(v);
    Wh[idx] = h;
    Wl[idx] = __float2half(v - __half2float(h));
}

__global__ void pack_u_kernel(const float* __restrict__ U,
                              __nv_bfloat16* __restrict__ Uh, __nv_bfloat16* __restrict__ Ul) {
    const int idx = blockIdx.x * blockDim.x + threadIdx.x;
    if (idx >= LL * DM * KW) return;
    const int i = idx / (DM * KW);
    const int rem = idx % (DM * KW);
    const int d = rem / KW, k = rem % KW;
    const float v = U[(((size_t)i * EE + (k >> 6)) * DM + d) * RR + (k & 63)];
    const __nv_bfloat16 h = __float2bfloat16(v);
    Uh[idx] = h;
    Ul[idx] = __float2bfloat16(v - __bfloat162float(h));
}

// ---------------------------------------------------------------------------
// Launch
// ---------------------------------------------------------------------------
extern "C" void kernel_launch(void* const* d_in, const int* in_sizes, int n_in,
                              void* d_out, int out_size) {
    const float* x0   = (const float*)d_in[0];
    const float* U    = (const float*)d_in[1];
    const float* V    = (const float*)d_in[2];
    const float* C    = (const float*)d_in[3];
    const float* gw   = (const float*)d_in[4];
    const float* bias = (const float*)d_in[5];
    float* out = (float*)d_out;

    float* Y = nullptr;
    __half *xh, *xl, *w1h, *w1l;
    __nv_bfloat16 *wh, *wl, *uh, *ul;
    cudaGetSymbolAddress((void**)&Y,   g_Y);
    cudaGetSymbolAddress((void**)&xh,  g_xh);
    cudaGetSymbolAddress((void**)&xl,  g_xl);
    cudaGetSymbolAddress((void**)&wh,  g_wh);
    cudaGetSymbolAddress((void**)&wl,  g_wl);
    cudaGetSymbolAddress((void**)&w1h, g_W1h);
    cudaGetSymbolAddress((void**)&w1l, g_W1l);
    cudaGetSymbolAddress((void**)&uh,  g_Uh);
    cudaGetSymbolAddress((void**)&ul,  g_Ul);

    // GEMM1: 3 stages * (128*144 + 2*64*144) = 110592 B -> 2 CTAs/SM
    // GEMM2: 2 stages * (2*128*80 + 2*128*80) = 81920 B -> 2 CTAs/SM
    constexpr int SMEM1 = 3 * (128 * 144 + 2 * 64 * 144);
    constexpr int SMEM2 = 2 * (2 * 128 * 80 + 2 * 128 * 80);
    cudaFuncSetAttribute((const void*)gemm1_f16,
                         cudaFuncAttributeMaxDynamicSharedMemorySize, SMEM1);
    cudaFuncSetAttribute((const void*)gemm2_bf16<1>,
                         cudaFuncAttributeMaxDynamicSharedMemorySize, SMEM2);
    cudaFuncSetAttribute((const void*)gemm2_bf16<2>,
                         cudaFuncAttributeMaxDynamicSharedMemorySize, SMEM2);
    cudaFuncSetAttribute((const void*)mix_kernel,
                         cudaFuncAttributeMaxDynamicSharedMemorySize, EE * RR * RR * 4);

    // Pack weights + initial x conversion
    pack_w1_kernel<<<(LL * NPAD * DM + 255) / 256, 256>>>(V, gw, w1h, w1l);
    pack_u_kernel<<<(LL * DM * KW + 255) / 256, 256>>>(U, uh, ul);
    conv_kernel<<<(BSZ * DM / 4) / 256, 256>>>(x0, xh, xl);

    for (int i = 0; i < LL; ++i) {
        // GEMM1: Y[B,320] = xh @ [V|gate]^T   (fp16 2-term, measured 72us)
        gemm1_f16<<<dim3(NPAD / 64, BSZ / 128), 256, SMEM1>>>(
            xh, w1h, w1l, i * NPAD, Y);

        // Mix: tanh -> C -> tanh -> softmax gates -> bf16 wh/wl
        mix_kernel<<<BSZ / 64, 256, EE * RR * RR * 4>>>(
            Y, C + (size_t)i * EE * RR * RR, wh, wl);

        // GEMM2 + fused epilogue (bf16x3, R8-proven): x_{l+1} = (xh+xl) + x0*(w@U^T + bias)
        if (i < LL - 1) {
            gemm2_bf16<1><<<dim3(DM / 128, BSZ / 128), 256, SMEM2>>>(
                wh, wl, uh, ul, i * DM,
                nullptr, x0, bias + (size_t)i * DM, xh, xl);
        } else {
            gemm2_bf16<2><<<dim3(DM / 128, BSZ / 128), 256, SMEM2>>>(
                wh, wl, uh, ul, i * DM,
                out, x0, bias + (size_t)i * DM, xh, xl);
        }
    }
}

// round 14
// speedup vs baseline: 3.6997x; 3.0955x over previous
#include <cuda_runtime.h>
#include <cuda_bf16.h>
#include <cstdint>
#include <cstddef>

// Problem constants
#define BSZ   16384
#define DM    1024
#define RR    64
#define EE    4
#define LL    3
#define NPAD  320     // 256 V cols + 4 gate cols, padded to 5*64
#define KW    256     // E*R

// ---------------------------------------------------------------------------
// Static device buffers (all bf16 — fp16 empirically toxic on this problem)
// ---------------------------------------------------------------------------
__device__ __align__(256) __nv_bfloat16  g_xh[(size_t)BSZ * DM];      // bf16 hi of x_l
__device__ __align__(256) __nv_bfloat16  g_xlo[(size_t)BSZ * DM];     // bf16 lo of x_l
__device__ __align__(256) float          g_Y[(size_t)BSZ * NPAD];
__device__ __align__(256) __nv_bfloat16  g_wh[(size_t)BSZ * KW];      // bf16 w (rounded)
__device__ __align__(256) __nv_bfloat16  g_W1h[LL * NPAD * DM];       // [n][d] rows
__device__ __align__(256) __nv_bfloat16  g_W1l[LL * NPAD * DM];
__device__ __align__(256) __nv_bfloat16  g_Uh[LL * DM * KW];          // [d][k] rows
__device__ __align__(256) __nv_bfloat16  g_Ul[LL * DM * KW];

// ---------------------------------------------------------------------------
// PTX helpers (baseline ISA only)
// ---------------------------------------------------------------------------
__device__ __forceinline__ uint32_t s2u(const void* p) {
    uint32_t a;
    asm("{ .reg .u64 t; cvta.to.shared.u64 t, %1; cvt.u32.u64 %0, t; }" : "=r"(a) : "l"(p));
    return a;
}
__device__ __forceinline__ void cpasync16(uint32_t dst, const void* src) {
    asm volatile("cp.async.cg.shared.global [%0], [%1], 16;" :: "r"(dst), "l"(src) : "memory");
}
#define CP_COMMIT() asm volatile("cp.async.commit_group;" ::: "memory")
#define CP_WAIT1()  asm volatile("cp.async.wait_group 1;" ::: "memory")

__device__ __forceinline__ void ldsm4(uint32_t* r, uint32_t addr) {
    asm volatile("ldmatrix.sync.aligned.m8n8.x4.shared.b16 {%0,%1,%2,%3}, [%4];"
                 : "=r"(r[0]), "=r"(r[1]), "=r"(r[2]), "=r"(r[3]) : "r"(addr));
}
__device__ __forceinline__ void mma_bf16(float* c, const uint32_t* a, const uint32_t* b) {
    asm volatile(
        "mma.sync.aligned.m16n8k16.row.col.f32.bf16.bf16.f32 "
        "{%0,%1,%2,%3}, {%4,%5,%6,%7}, {%8,%9}, {%0,%1,%2,%3};"
        : "+f"(c[0]), "+f"(c[1]), "+f"(c[2]), "+f"(c[3])
        : "r"(a[0]), "r"(a[1]), "r"(a[2]), "r"(a[3]), "r"(b[0]), "r"(b[1]));
}

// FMA-only tanh (no MUFU): tanh(x) = sgn(x)*(1 - 2/(e^{2|x|}+1))
__device__ __forceinline__ float fast_tanh(float x) {
    float ax = fminf(fabsf(x), 9.0f);
    float z = ax * 2.885390082f;                 // 2*log2(e)*|x|
    float k2 = z + 12582912.0f;                  // 1.5*2^23 round trick
    int   ki = __float_as_int(k2) - 0x4B400000;
    float f  = z - (k2 - 12582912.0f);           // frac in [-0.5, 0.5]
    float p = 1.3333558e-3f;
    p = fmaf(p, f, 9.6181291e-3f);
    p = fmaf(p, f, 5.5504109e-2f);
    p = fmaf(p, f, 2.4022651e-1f);
    p = fmaf(p, f, 6.9314718e-1f);
    p = fmaf(p, f, 1.0f);
    float E = p * __int_as_float((ki + 127) << 23);   // e^{2|x|}
    float d = E + 1.0f;
    float r = __int_as_float(0x7EF311C3 - __float_as_int(d));
    r = r * fmaf(-d, r, 2.0f);
    r = r * fmaf(-d, r, 2.0f);
    r = r * fmaf(-d, r, 2.0f);
    float t = fmaf(-2.0f, r, 1.0f);
    return copysignf(t, x);
}

// ---------------------------------------------------------------------------
// GEMM1 (R7/R8-proven, 107.8us): bf16 3-term, D = (Ah+Al)@(Bh+Bl)^T (drop Al*Bl)
// BM=128, BN=64, WN=32, BK=64 (pitch 144), 2-stage cp.async, 2 CTAs/SM.
// Writes fp32 D to Cout (ld = NPAD).
// ---------------------------------------------------------------------------
__global__ void __launch_bounds__(256, 2)
gemm1_bf16(const __nv_bfloat16* __restrict__ Agh, const __nv_bfloat16* __restrict__ Agl,
           const __nv_bfloat16* __restrict__ Bgh, const __nv_bfloat16* __restrict__ Bgl,
           int bRowOff, float* __restrict__ Cout)
{
    constexpr int BM = 128, BN = 64, WN = 32, BK = 64, KTOT = DM;
    constexpr int MF = 2, NF = WN / 8, KS = BK / 16, KCH = KTOT / BK;
    constexpr int PITCH = 2 * BK + 16;       // 144
    constexpr int SA = BM * PITCH, SB = BN * PITCH, SST = 2 * SA + 2 * SB;

    extern __shared__ __align__(128) char smem[];
    const uint32_t sbase = s2u(smem);

    const int tid = threadIdx.x, lane = tid & 31, wid = tid >> 5;
    const int wm = wid & 3, wn = wid >> 2;
    const int m0 = blockIdx.y * BM;
    const int n0 = bRowOff + blockIdx.x * BN;
    const int c0 = blockIdx.x * BN;
    const int K = KTOT;

    float acc[MF][NF][4];
#pragma unroll
    for (int i = 0; i < MF; ++i)
#pragma unroll
        for (int j = 0; j < NF; ++j)
#pragma unroll
            for (int p = 0; p < 4; ++p) acc[i][j][p] = 0.f;

    auto load_stage = [&](int st, int kt) {
        const uint32_t base = sbase + st * SST;
        const int kk = kt * BK;
        constexpr int CPR = BK / 8;       // 8
#pragma unroll
        for (int c = tid; c < BM * CPR; c += 256) {
            const int row = c / CPR, cc = c % CPR;
            const size_t g = (size_t)(m0 + row) * K + kk + cc * 8;
            const uint32_t s = row * PITCH + cc * 16;
            cpasync16(base + s,      Agh + g);
            cpasync16(base + SA + s, Agl + g);
        }
#pragma unroll
        for (int c = tid; c < BN * CPR; c += 256) {
            const int row = c / CPR, cc = c % CPR;
            const size_t g = (size_t)(n0 + row) * K + kk + cc * 8;
            const uint32_t s = row * PITCH + cc * 16;
            cpasync16(base + 2 * SA + s,      Bgh + g);
            cpasync16(base + 2 * SA + SB + s, Bgl + g);
        }
    };

    load_stage(0, 0);
    CP_COMMIT();

    const int arow = wm * 32 + (lane & 15);
    const int brow = wn * WN + (lane & 7) + ((lane >> 4) << 3);
    const uint32_t aoff = (uint32_t)arow * PITCH + ((lane >> 4) << 4);
    const uint32_t boff = (uint32_t)brow * PITCH + (((lane >> 3) & 1) << 4);

    for (int kt = 0; kt < KCH; ++kt) {
        if (kt + 1 < KCH) load_stage((kt + 1) & 1, kt + 1);
        CP_COMMIT();
        CP_WAIT1();
        __syncthreads();

        const uint32_t sb2 = sbase + (kt & 1) * SST;
        const uint32_t ab = sb2 + aoff;
        const uint32_t bb = sb2 + 2 * SA + boff;

#pragma unroll
        for (int ks = 0; ks < KS; ++ks) {
            uint32_t ah[MF][4], al[MF][4];
#pragma unroll
            for (int mf = 0; mf < MF; ++mf) {
                const uint32_t off = ab + mf * 16 * PITCH + ks * 32;
                ldsm4(ah[mf], off);
                ldsm4(al[mf], off + SA);
            }
            uint32_t bh[NF][2], bl[NF][2];
#pragma unroll
            for (int nf2 = 0; nf2 < NF / 2; ++nf2) {
                const uint32_t off = bb + nf2 * 16 * PITCH + ks * 32;
                uint32_t t[4];
                ldsm4(t, off);
                bh[2 * nf2][0] = t[0]; bh[2 * nf2][1] = t[1];
                bh[2 * nf2 + 1][0] = t[2]; bh[2 * nf2 + 1][1] = t[3];
                ldsm4(t, off + SB);
                bl[2 * nf2][0] = t[0]; bl[2 * nf2][1] = t[1];
                bl[2 * nf2 + 1][0] = t[2]; bl[2 * nf2 + 1][1] = t[3];
            }
#pragma unroll
            for (int mf = 0; mf < MF; ++mf)
#pragma unroll
                for (int nf = 0; nf < NF; ++nf) {
                    mma_bf16(acc[mf][nf], ah[mf], bh[nf]);
                    mma_bf16(acc[mf][nf], ah[mf], bl[nf]);
                    mma_bf16(acc[mf][nf], al[mf], bh[nf]);
                }
        }
        __syncthreads();
    }

#pragma unroll
    for (int mf = 0; mf < MF; ++mf)
#pragma unroll
        for (int p = 0; p < 2; ++p) {
            const int m = m0 + wm * 32 + mf * 16 + (lane >> 2) + p * 8;
#pragma unroll
            for (int nf = 0; nf < NF; ++nf) {
                const int col = c0 + wn * WN + nf * 8 + (lane & 3) * 2;
                *reinterpret_cast<float2*>(Cout + (size_t)m * NPAD + col) =
                    make_float2(acc[mf][nf][p * 2], acc[mf][nf][p * 2 + 1]);
            }
        }
}

// ---------------------------------------------------------------------------
// GEMM2: bf16 2-term, A single (wh), B split (Uh+Ul): D = A@(Bh+Bl)^T.
// Dropped term = wl*U ~ 2^-9 relative of D; D enters output as small
// correction (x0*D ~ 0.06*x), final rel-err contribution ~1e-4.
// BM=128, BN=128, WN=64, BK=32 (pitch 80), 2-stage cp.async, 2 CTAs/SM.
// Epilogue: o = (xh+xlo) + x0*(D+bias); MODE 1 writes bf16 xh/xlo = split(o),
// MODE 2 writes fp32 o to Cout.
// ---------------------------------------------------------------------------
template <int MODE>
__global__ void __launch_bounds__(256, 2)
gemm2_bf16(const __nv_bfloat16* __restrict__ Ag,
           const __nv_bfloat16* __restrict__ Bgh, const __nv_bfloat16* __restrict__ Bgl,
           int bRowOff, float* __restrict__ Cout,
           const float* __restrict__ x0, const float* __restrict__ bias,
           __nv_bfloat16* __restrict__ xh, __nv_bfloat16* __restrict__ xl)
{
    constexpr int BM = 128, BN = 128, WN = 64, BK = 32, KTOT = KW;
    constexpr int MF = 2, NF = WN / 8, KS = BK / 16, KCH = KTOT / BK;
    constexpr int PITCH = 2 * BK + 16;       // 80
    constexpr int SA = BM * PITCH, SB = BN * PITCH, SST = SA + 2 * SB;

    extern __shared__ __align__(128) char smem[];
    const uint32_t sbase = s2u(smem);

    const int tid = threadIdx.x, lane = tid & 31, wid = tid >> 5;
    const int wm = wid & 3, wn = wid >> 2;
    const int m0 = blockIdx.y * BM;
    const int n0 = bRowOff + blockIdx.x * BN;
    const int c0 = blockIdx.x * BN;
    const int K = KTOT;

    float acc[MF][NF][4];
#pragma unroll
    for (int i = 0; i < MF; ++i)
#pragma unroll
        for (int j = 0; j < NF; ++j)
#pragma unroll
            for (int p = 0; p < 4; ++p) acc[i][j][p] = 0.f;

    auto load_stage = [&](int st, int kt) {
        const uint32_t base = sbase + st * SST;
        const int kk = kt * BK;
        constexpr int CPR = BK / 8;      // 4
#pragma unroll
        for (int c = tid; c < BM * CPR; c += 256) {
            const int row = c / CPR, cc = c % CPR;
            cpasync16(base + row * PITCH + cc * 16,
                      Ag + (size_t)(m0 + row) * K + kk + cc * 8);
        }
#pragma unroll
        for (int c = tid; c < BN * CPR; c += 256) {
            const int row = c / CPR, cc = c % CPR;
            const size_t g = (size_t)(n0 + row) * K + kk + cc * 8;
            const uint32_t s = row * PITCH + cc * 16;
            cpasync16(base + SA + s,      Bgh + g);
            cpasync16(base + SA + SB + s, Bgl + g);
        }
    };

    load_stage(0, 0);
    CP_COMMIT();

    const int arow = wm * 32 + (lane & 15);
    const int brow = wn * WN + (lane & 7) + ((lane >> 4) << 3);
    const uint32_t aoff = (uint32_t)arow * PITCH + ((lane >> 4) << 4);
    const uint32_t boff = (uint32_t)brow * PITCH + (((lane >> 3) & 1) << 4);

    for (int kt = 0; kt < KCH; ++kt) {
        if (kt + 1 < KCH) load_stage((kt + 1) & 1, kt + 1);
        CP_COMMIT();
        CP_WAIT1();
        __syncthreads();

        const uint32_t sb2 = sbase + (kt & 1) * SST;
        const uint32_t ab = sb2 + aoff;
        const uint32_t bb = sb2 + SA + boff;

#pragma unroll
        for (int ks = 0; ks < KS; ++ks) {
            uint32_t af[MF][4];
#pragma unroll
            for (int mf = 0; mf < MF; ++mf)
                ldsm4(af[mf], ab + mf * 16 * PITCH + ks * 32);
            uint32_t bh[NF][2], bl[NF][2];
#pragma unroll
            for (int nf2 = 0; nf2 < NF / 2; ++nf2) {
                const uint32_t off = bb + nf2 * 16 * PITCH + ks * 32;
                uint32_t t[4];
                ldsm4(t, off);
                bh[2 * nf2][0] = t[0]; bh[2 * nf2][1] = t[1];
                bh[2 * nf2 + 1][0] = t[2]; bh[2 * nf2 + 1][1] = t[3];
                ldsm4(t, off + SB);
                bl[2 * nf2][0] = t[0]; bl[2 * nf2][1] = t[1];
                bl[2 * nf2 + 1][0] = t[2]; bl[2 * nf2 + 1][1] = t[3];
            }
#pragma unroll
            for (int mf = 0; mf < MF; ++mf)
#pragma unroll
                for (int nf = 0; nf < NF; ++nf)
                    mma_bf16(acc[mf][nf], af[mf], bh[nf]);
#pragma unroll
            for (int mf = 0; mf < MF; ++mf)
#pragma unroll
                for (int nf = 0; nf < NF; ++nf)
                    mma_bf16(acc[mf][nf], af[mf], bl[nf]);
        }
        __syncthreads();
    }

    // Epilogue: o = (xh+xlo) + x0*(D+bias)
#pragma unroll
    for (int mf = 0; mf < MF; ++mf)
#pragma unroll
        for (int p = 0; p < 2; ++p) {
            const int m = m0 + wm * 32 + mf * 16 + (lane >> 2) + p * 8;
#pragma unroll
            for (int nf = 0; nf < NF; ++nf) {
                const int col = c0 + wn * WN + nf * 8 + (lane & 3) * 2;
                const size_t off = (size_t)m * DM + col;
                const float v0 = acc[mf][nf][p * 2];
                const float v1 = acc[mf][nf][p * 2 + 1];
                const float2 xz = *reinterpret_cast<const float2*>(x0 + off);
                const float2 bb2 = *reinterpret_cast<const float2*>(bias + col);
                const __nv_bfloat162 hv = *reinterpret_cast<const __nv_bfloat162*>(xh + off);
                const __nv_bfloat162 lv = *reinterpret_cast<const __nv_bfloat162*>(xl + off);
                const float xp0 = __bfloat162float(hv.x) + __bfloat162float(lv.x);
                const float xp1 = __bfloat162float(hv.y) + __bfloat162float(lv.y);
                const float o0 = fmaf(xz.x, v0 + bb2.x, xp0);
                const float o1 = fmaf(xz.y, v1 + bb2.y, xp1);
                if constexpr (MODE == 1) {
                    const __nv_bfloat16 h0 = __float2bfloat16(o0);
                    const __nv_bfloat16 h1 = __float2bfloat16(o1);
                    __nv_bfloat162 hp; hp.x = h0; hp.y = h1;
                    *reinterpret_cast<__nv_bfloat162*>(xh + off) = hp;
                    __nv_bfloat162 lp;
                    lp.x = __float2bfloat16(o0 - __bfloat162float(h0));
                    lp.y = __float2bfloat16(o1 - __bfloat162float(h1));
                    *reinterpret_cast<__nv_bfloat162*>(xl + off) = lp;
                } else {
                    *reinterpret_cast<float2*>(Cout + off) = make_float2(o0, o1);
                }
            }
        }
}

// ---------------------------------------------------------------------------
// Mix kernel: vt=tanh(Y) -> v2=tanh(C vt) -> softmax gates -> bf16 wh (single)
// ---------------------------------------------------------------------------
__global__ void __launch_bounds__(256) mix_kernel(const float* __restrict__ Y,
                                                  const float* __restrict__ Cl,
                                                  __nv_bfloat16* __restrict__ Wh)
{
    extern __shared__ float Cs[];          // 64 KB: Cs[(e*64+s)*64 + r] = C[e,r,s]
    __shared__ float vt[8][EE * RR];
    __shared__ float gs[8][EE];

    const int tid = threadIdx.x;
    for (int idx = tid; idx < EE * RR * RR; idx += 256) {
        int e = idx >> 12, rem = idx & 4095, s = rem >> 6, r = rem & 63;
        Cs[idx] = Cl[((size_t)e * RR + r) * RR + s];
    }
    __syncthreads();

    const int e = tid >> 6;
    const float* cp = Cs + e * (RR * RR) + (tid & 63);
    const int row0 = blockIdx.x * 64;

    for (int it = 0; it < 8; ++it) {
        const int row = row0 + it * 8;
#pragma unroll
        for (int q = 0; q < 8; ++q)
            vt[q][tid] = fast_tanh(Y[(size_t)(row + q) * NPAD + tid]);
        if (tid < 8) {
            const float* yr = Y + (size_t)(row + tid) * NPAD + EE * RR;
            const float l0 = yr[0], l1 = yr[1], l2 = yr[2], l3 = yr[3];
            const float mx = fmaxf(fmaxf(l0, l1), fmaxf(l2, l3));
            const float e0 = __expf(l0 - mx), e1 = __expf(l1 - mx);
            const float e2 = __expf(l2 - mx), e3 = __expf(l3 - mx);
            const float inv = __frcp_rn(e0 + e1 + e2 + e3);
            gs[tid][0] = e0 * inv; gs[tid][1] = e1 * inv;
            gs[tid][2] = e2 * inv; gs[tid][3] = e3 * inv;
        }
        __syncthreads();

        float a[8];
#pragma unroll
        for (int q = 0; q < 8; ++q) a[q] = 0.f;
#pragma unroll
        for (int s = 0; s < RR; ++s) {
            const float c = cp[s * RR];
#pragma unroll
            for (int q = 0; q < 8; ++q)
                a[q] = fmaf(c, vt[q][e * RR + s], a[q]);
        }
#pragma unroll
        for (int q = 0; q < 8; ++q) {
            const float w = gs[q][e] * fast_tanh(a[q]);
            Wh[(size_t)(row + q) * KW + tid] = __float2bfloat16(w);
        }
        __syncthreads();
    }
}

// ---------------------------------------------------------------------------
// Conversion + weight packing (all bf16, R8 verbatim)
// ---------------------------------------------------------------------------
__global__ void conv_kernel(const float* __restrict__ x,
                            __nv_bfloat16* __restrict__ xh,
                            __nv_bfloat16* __restrict__ xl) {
    const size_t i = ((size_t)blockIdx.x * blockDim.x + threadIdx.x) * 4;
    const float4 v = *reinterpret_cast<const float4*>(x + i);
    __nv_bfloat16 h0 = __float2bfloat16(v.x), h1 = __float2bfloat16(v.y);
    __nv_bfloat16 h2 = __float2bfloat16(v.z), h3 = __float2bfloat16(v.w);
    __nv_bfloat162 hp0; hp0.x = h0; hp0.y = h1;
    __nv_bfloat162 hp1; hp1.x = h2; hp1.y = h3;
    *reinterpret_cast<__nv_bfloat162*>(xh + i)     = hp0;
    *reinterpret_cast<__nv_bfloat162*>(xh + i + 2) = hp1;
    __nv_bfloat162 lp0, lp1;
    lp0.x = __float2bfloat16(v.x - __bfloat162float(h0));
    lp0.y = __float2bfloat16(v.y - __bfloat162float(h1));
    lp1.x = __float2bfloat16(v.z - __bfloat162float(h2));
    lp1.y = __float2bfloat16(v.w - __bfloat162float(h3));
    *reinterpret_cast<__nv_bfloat162*>(xl + i)     = lp0;
    *reinterpret_cast<__nv_bfloat162*>(xl + i + 2) = lp1;
}

__global__ void pack_w1_kernel(const float* __restrict__ V, const float* __restrict__ gw,
                               __nv_bfloat16* __restrict__ Wh, __nv_bfloat16* __restrict__ Wl) {
    const int idx = blockIdx.x * blockDim.x + threadIdx.x;
    if (idx >= LL * NPAD * DM) return;
    const int i = idx / (NPAD * DM);
    const int rem = idx % (NPAD * DM);
    const int n = rem / DM, d = rem % DM;
    float v = 0.f;
    if (n < EE * RR)
        v = V[(((size_t)i * EE + (n >> 6)) * DM + d) * RR + (n & 63)];
    else if (n < EE * RR + EE)
        v = gw[(size_t)(n - EE * RR) * DM + d];
    const __nv_bfloat16 h = __float2bfloat16(v);
    Wh[idx] = h;
    Wl[idx] = __float2bfloat16(v - __bfloat162float(h));
}

__global__ void pack_u_kernel(const float* __restrict__ U,
                              __nv_bfloat16* __restrict__ Uh, __nv_bfloat16* __restrict__ Ul) {
    const int idx = blockIdx.x * blockDim.x + threadIdx.x;
    if (idx >= LL * DM * KW) return;
    const int i = idx / (DM * KW);
    const int rem = idx % (DM * KW);
    const int d = rem / KW, k = rem % KW;
    const float v = U[(((size_t)i * EE + (k >> 6)) * DM + d) * RR + (k & 63)];
    const __nv_bfloat16 h = __float2bfloat16(v);
    Uh[idx] = h;
    Ul[idx] = __float2bfloat16(v - __bfloat162float(h));
}

// ---------------------------------------------------------------------------
// Launch
// ---------------------------------------------------------------------------
extern "C" void kernel_launch(void* const* d_in, const int* in_sizes, int n_in,
                              void* d_out, int out_size) {
    const float* x0   = (const float*)d_in[0];
    const float* U    = (const float*)d_in[1];
    const float* V    = (const float*)d_in[2];
    const float* C    = (const float*)d_in[3];
    const float* gw   = (const float*)d_in[4];
    const float* bias = (const float*)d_in[5];
    float* out = (float*)d_out;

    float* Y = nullptr;
    __nv_bfloat16 *xh, *xl, *wh, *w1h, *w1l, *uh, *ul;
    cudaGetSymbolAddress((void**)&Y,   g_Y);
    cudaGetSymbolAddress((void**)&xh,  g_xh);
    cudaGetSymbolAddress((void**)&xl,  g_xlo);
    cudaGetSymbolAddress((void**)&wh,  g_wh);
    cudaGetSymbolAddress((void**)&w1h, g_W1h);
    cudaGetSymbolAddress((void**)&w1l, g_W1l);
    cudaGetSymbolAddress((void**)&uh,  g_Uh);
    cudaGetSymbolAddress((void**)&ul,  g_Ul);

    // GEMM1: 2 stages * (2*128*144 + 2*64*144) = 110592 B -> 2 CTAs/SM (R8-proven)
    // GEMM2: 2 stages * (128*80 + 2*128*80)    =  61440 B -> 2 CTAs/SM
    constexpr int SMEM1 = 2 * (2 * 128 * 144 + 2 * 64 * 144);
    constexpr int SMEM2 = 2 * (128 * 80 + 2 * 128 * 80);
    cudaFuncSetAttribute((const void*)gemm1_bf16,
                         cudaFuncAttributeMaxDynamicSharedMemorySize, SMEM1);
    cudaFuncSetAttribute((const void*)gemm2_bf16<1>,
                         cudaFuncAttributeMaxDynamicSharedMemorySize, SMEM2);
    cudaFuncSetAttribute((const void*)gemm2_bf16<2>,
                         cudaFuncAttributeMaxDynamicSharedMemorySize, SMEM2);
    cudaFuncSetAttribute((const void*)mix_kernel,
                         cudaFuncAttributeMaxDynamicSharedMemorySize, EE * RR * RR * 4);

    // Pack weights + initial x conversion
    pack_w1_kernel<<<(LL * NPAD * DM + 255) / 256, 256>>>(V, gw, w1h, w1l);
    pack_u_kernel<<<(LL * DM * KW + 255) / 256, 256>>>(U, uh, ul);
    conv_kernel<<<(BSZ * DM / 4) / 256, 256>>>(x0, xh, xl);

    for (int i = 0; i < LL; ++i) {
        // GEMM1: Y[B,320] = x @ [V|gate]^T   (bf16 3-term, R8-proven)
        gemm1_bf16<<<dim3(NPAD / 64, BSZ / 128), 256, SMEM1>>>(
            xh, xl, w1h, w1l, i * NPAD, Y);

        // Mix: tanh -> C -> tanh -> softmax gates -> bf16 wh
        mix_kernel<<<BSZ / 64, 256, EE * RR * RR * 4>>>(
            Y, C + (size_t)i * EE * RR * RR, wh);

        // GEMM2 + fused epilogue: x_{l+1} = (xh+xlo) + x0*(wh @ (Uh+Ul)^T + bias)
        if (i < LL - 1) {
            gemm2_bf16<1><<<dim3(DM / 128, BSZ / 128), 256, SMEM2>>>(
                wh, uh, ul, i * DM,
                nullptr, x0, bias + (size_t)i * DM, xh, xl);
        } else {
            gemm2_bf16<2><<<dim3(DM / 128, BSZ / 128), 256, SMEM2>>>(
                wh, uh, ul, i * DM,
                out, x0, bias + (size_t)i * DM, xh, xl);
        }
    }
}